// round 13
// baseline (speedup 1.0000x reference)
#include <cuda_runtime.h>
#include <cuda_bf16.h>
#include <cstdint>

#define B_  32
#define T_  12
#define N_  1024
#define F_  64
#define TO_ 768   // T_*O

// ---------------- device scratch (allocation-free rule) ----------------
__device__ __align__(16) __nv_bfloat16 g_Ah[(size_t)B_ * N_ * N_];
__device__ __align__(16) __nv_bfloat16 g_Al[(size_t)B_ * N_ * N_];
__device__ __align__(16) __nv_bfloat16 g_R2h[(size_t)B_ * TO_ * N_];
__device__ __align__(16) __nv_bfloat16 g_R2l[(size_t)B_ * TO_ * N_];
__device__ __align__(16) __nv_bfloat16 g_Zh[(size_t)B_ * TO_ * N_];
__device__ __align__(16) __nv_bfloat16 g_Zl[(size_t)B_ * TO_ * N_];
__device__ __align__(16) float g_R1t[(size_t)B_ * TO_ * N_];
__device__ __align__(16) float g_Dt [(size_t)B_ * TO_ * N_];
__device__ float g_lam[B_];

// ---------------- PTX helpers ----------------
__device__ __forceinline__ uint32_t smem_u32(const void* p) {
    uint32_t a;
    asm("{ .reg .u64 t; cvta.to.shared.u64 t, %1; cvt.u32.u64 %0, t; }" : "=r"(a) : "l"(p));
    return a;
}
#define CP16(dst, src) asm volatile("cp.async.cg.shared.global [%0], [%1], 16;" :: "r"(dst), "l"(src))
#define CP_COMMIT() asm volatile("cp.async.commit_group;" ::: "memory")
#define CP_WAIT(n)  asm volatile("cp.async.wait_group %0;" :: "n"(n) : "memory")

__device__ __forceinline__ void ldsm4(unsigned* r, uint32_t addr) {
    asm volatile("ldmatrix.sync.aligned.m8n8.x4.shared.b16 {%0,%1,%2,%3}, [%4];"
                 : "=r"(r[0]), "=r"(r[1]), "=r"(r[2]), "=r"(r[3]) : "r"(addr));
}
__device__ __forceinline__ void mma16816(float* c, const unsigned* a, const unsigned* b) {
    asm volatile("mma.sync.aligned.m16n8k16.row.col.f32.bf16.bf16.f32 "
                 "{%0,%1,%2,%3}, {%4,%5,%6,%7}, {%8,%9}, {%0,%1,%2,%3};"
                 : "+f"(c[0]), "+f"(c[1]), "+f"(c[2]), "+f"(c[3])
                 : "r"(a[0]), "r"(a[1]), "r"(a[2]), "r"(a[3]), "r"(b[0]), "r"(b[1]));
}
__device__ __forceinline__ void split_bf16x4(float4 v, uint2& h, uint2& l) {
    __nv_bfloat16 h0 = __float2bfloat16(v.x), h1 = __float2bfloat16(v.y);
    __nv_bfloat16 h2 = __float2bfloat16(v.z), h3 = __float2bfloat16(v.w);
    __nv_bfloat16 l0 = __float2bfloat16(v.x - __bfloat162float(h0));
    __nv_bfloat16 l1 = __float2bfloat16(v.y - __bfloat162float(h1));
    __nv_bfloat16 l2 = __float2bfloat16(v.z - __bfloat162float(h2));
    __nv_bfloat16 l3 = __float2bfloat16(v.w - __bfloat162float(h3));
    h.x = ((unsigned)__bfloat16_as_ushort(h1) << 16) | __bfloat16_as_ushort(h0);
    h.y = ((unsigned)__bfloat16_as_ushort(h3) << 16) | __bfloat16_as_ushort(h2);
    l.x = ((unsigned)__bfloat16_as_ushort(l1) << 16) | __bfloat16_as_ushort(l0);
    l.y = ((unsigned)__bfloat16_as_ushort(l3) << 16) | __bfloat16_as_ushort(l2);
}

// ---------------- lambda init + rowsum + A split ----------------
__global__ void lam_init_kernel() {
    if (threadIdx.x < B_) g_lam[threadIdx.x] = 1.0f;
}

__global__ __launch_bounds__(256) void rowsum_conv_kernel(const float* __restrict__ A) {
    __shared__ float red[8];
    int row = blockIdx.x;
    int b = row >> 10;
    int t = threadIdx.x;
    const float4* ap = (const float4*)(A + (size_t)row * N_);
    float4 v = ap[t];
    uint2 h, l;
    split_bf16x4(v, h, l);
    ((uint2*)g_Ah)[(size_t)row * 256 + t] = h;
    ((uint2*)g_Al)[(size_t)row * 256 + t] = l;

    float s = v.x + v.y + v.z + v.w;
#pragma unroll
    for (int off = 16; off > 0; off >>= 1) s += __shfl_xor_sync(0xFFFFFFFF, s, off);
    if ((t & 31) == 0) red[t >> 5] = s;
    __syncthreads();
    if (t < 8) {
        float ss = red[t];
#pragma unroll
        for (int off = 4; off > 0; off >>= 1) ss += __shfl_xor_sync(0xFF, ss, off);
        if (t == 0) atomicMax((int*)&g_lam[b], __float_as_int(ss));
    }
}

// ---------------- feat on HMMA: out[row, c] = x[row,:64] @ W[:64, c], c in 0..191 ----------------
#define F_WH  0
#define F_WL  24576
#define F_XH  49152
#define F_XL  65536
#define F_RA  81920
#define FEAT_SMEM (81920 + 50688)

__global__ __launch_bounds__(256) void feat_mma(const float* __restrict__ x,
                                                const float* __restrict__ Th) {
    extern __shared__ __align__(1024) char fs[];
    uint32_t sb = smem_u32(fs);
    int tid = threadIdx.x, lane = tid & 31, wid = tid >> 5;
    int wr = wid & 3, wh = wid >> 2;

    float* sWf = (float*)(fs + F_RA);   // [64][196]
    for (int i = tid; i < 64 * 192; i += 256) {
        int f = i / 192, c = i % 192;
        int k = c >> 6, o = c & 63;
        float v;
        if (k == 0) v = Th[f * 64 + o] - Th[2 * 4096 + f * 64 + o];
        else        v = Th[k * 4096 + f * 64 + o];
        sWf[f * 196 + c] = v;
    }
    __syncthreads();
    for (int task = tid; task < 1536; task += 256) {
        int c = task >> 3, ch = task & 7;
        float4 v0, v1;
        v0.x = sWf[(ch * 8 + 0) * 196 + c]; v0.y = sWf[(ch * 8 + 1) * 196 + c];
        v0.z = sWf[(ch * 8 + 2) * 196 + c]; v0.w = sWf[(ch * 8 + 3) * 196 + c];
        v1.x = sWf[(ch * 8 + 4) * 196 + c]; v1.y = sWf[(ch * 8 + 5) * 196 + c];
        v1.z = sWf[(ch * 8 + 6) * 196 + c]; v1.w = sWf[(ch * 8 + 7) * 196 + c];
        uint2 h0, l0, h1, l1;
        split_bf16x4(v0, h0, l0);
        split_bf16x4(v1, h1, l1);
        uint32_t addr = (uint32_t)(c * 128 + ((ch ^ (c & 7)) << 4));
        *(uint4*)(fs + F_WH + addr) = make_uint4(h0.x, h0.y, h1.x, h1.y);
        *(uint4*)(fs + F_WL + addr) = make_uint4(l0.x, l0.y, l1.x, l1.y);
    }

    int a_r = (lane & 7) + ((lane >> 3) & 1) * 8;
    int a_c = lane >> 4;
    int b_r = (lane & 7) + (lane >> 4) * 8;
    int b_c = (lane >> 3) & 1;
    int rr = lane >> 2, cc = (lane & 3) * 2;

    for (int tile = 0; tile < 4; tile++) {
        int rows_base = blockIdx.x * 512 + tile * 128;
        __syncthreads();
        for (int task = tid; task < 1024; task += 256) {
            int r = task >> 3, ch = task & 7;
            const float4* px = (const float4*)(x + (size_t)(rows_base + r) * 64 + ch * 8);
            float4 v0 = px[0], v1 = px[1];
            uint2 h0, l0, h1, l1;
            split_bf16x4(v0, h0, l0);
            split_bf16x4(v1, h1, l1);
            uint32_t addr = (uint32_t)(r * 128 + ((ch ^ (r & 7)) << 4));
            *(uint4*)(fs + F_XH + addr) = make_uint4(h0.x, h0.y, h1.x, h1.y);
            *(uint4*)(fs + F_XL + addr) = make_uint4(l0.x, l0.y, l1.x, l1.y);
        }
        __syncthreads();

        float acc[2][12][4];
#pragma unroll
        for (int i = 0; i < 2; i++)
#pragma unroll
            for (int j = 0; j < 12; j++)
#pragma unroll
                for (int q = 0; q < 4; q++) acc[i][j][q] = 0.f;

#pragma unroll
        for (int kk = 0; kk < 4; kk++) {
            unsigned ah[2][4], al[2][4], bh[6][4], bl[6][4];
#pragma unroll
            for (int i = 0; i < 2; i++) {
                int row = wr * 32 + 16 * i + a_r;
                int chunk = kk * 2 + a_c;
                uint32_t addr = (uint32_t)(row * 128 + ((chunk ^ (row & 7)) << 4));
                ldsm4(ah[i], sb + F_XH + addr);
                ldsm4(al[i], sb + F_XL + addr);
            }
#pragma unroll
            for (int jj = 0; jj < 6; jj++) {
                int row = wh * 96 + 16 * jj + b_r;
                int chunk = kk * 2 + b_c;
                uint32_t addr = (uint32_t)(row * 128 + ((chunk ^ (row & 7)) << 4));
                ldsm4(bh[jj], sb + F_WH + addr);
                ldsm4(bl[jj], sb + F_WL + addr);
            }
#pragma unroll
            for (int p = 0; p < 3; p++)
#pragma unroll
                for (int i = 0; i < 2; i++)
#pragma unroll
                    for (int j = 0; j < 12; j++) {
                        const unsigned* pa = (p < 2) ? ah[i] : al[i];
                        const unsigned* pb = (p == 1) ? &bl[j >> 1][(j & 1) * 2]
                                                      : &bh[j >> 1][(j & 1) * 2];
                        mma16816(acc[i][j], pa, pb);
                    }
        }

        int bt = rows_base >> 10;
        int bb = bt / T_, tt = bt % T_;
        int n0 = rows_base & 1023;
        float* sT = (float*)(fs + F_RA);   // [96][132]
        for (int half = 0; half < 2; half++) {
            __syncthreads();
            if (wh == half) {
#pragma unroll
                for (int i = 0; i < 2; i++)
#pragma unroll
                    for (int j = 0; j < 12; j++)
#pragma unroll
                        for (int h = 0; h < 2; h++) {
                            int row = wr * 32 + 16 * i + rr + 8 * h;
                            int col = 8 * j + cc;
                            sT[col * 132 + row]       = acc[i][j][2 * h + 0];
                            sT[(col + 1) * 132 + row] = acc[i][j][2 * h + 1];
                        }
            }
            __syncthreads();
            for (int task = tid; task < 1536; task += 256) {
                int cl = task >> 4, ch8 = task & 15;
                int c = half * 96 + cl;
                int k = c >> 6, o = c & 63;
                const float* src = &sT[cl * 132 + ch8 * 8];
                size_t gi = ((size_t)bb * TO_ + tt * 64 + o) * N_ + n0 + ch8 * 8;
                float4 v0 = make_float4(src[0], src[1], src[2], src[3]);
                float4 v1 = make_float4(src[4], src[5], src[6], src[7]);
                if (k < 2) {
                    float* dst = (k == 0) ? g_Dt : g_R1t;
                    *(float4*)&dst[gi]     = v0;
                    *(float4*)&dst[gi + 4] = v1;
                } else {
                    uint2 h0, l0, h1, l1;
                    split_bf16x4(v0, h0, l0);
                    split_bf16x4(v1, h1, l1);
                    *(uint4*)&g_R2h[gi] = make_uint4(h0.x, h0.y, h1.x, h1.y);
                    *(uint4*)&g_R2l[gi] = make_uint4(l0.x, l0.y, l1.x, l1.y);
                }
            }
        }
    }
}

// ---------------- HMMA GEMM: C[128x256] = A[b] @ Bsrc[b], split-bf16 x3 ----------------
// 512 threads, 4x4 warps, warp tile 32x64, 2-stage BK=64 pipeline, fill-before-MMA
#define SA_L 16384
#define SB_H 32768
#define SB_L 65536
#define STAGE_BYTES 98304
#define GEMM_SMEM   (2 * STAGE_BYTES)

__device__ __forceinline__ void fill_stage(uint32_t st, int kt, int bm0, int bn0,
                                           const __nv_bfloat16* __restrict__ Ah,
                                           const __nv_bfloat16* __restrict__ Al,
                                           const __nv_bfloat16* __restrict__ Bh,
                                           const __nv_bfloat16* __restrict__ Bl, int tid) {
    int ch = tid & 7, r0 = tid >> 3;   // r0: 0..63
    // A: 128 rows
#pragma unroll
    for (int i = 0; i < 2; i++) {
        int row = r0 + 64 * i;
        uint32_t sw = (uint32_t)(row * 128 + ((ch ^ (row & 7)) << 4));
        size_t ao = (size_t)(bm0 + row) * N_ + kt + ch * 8;
        CP16(st + sw,        Ah + ao);
        CP16(st + SA_L + sw, Al + ao);
    }
    // B: 256 rows
#pragma unroll
    for (int i = 0; i < 4; i++) {
        int row = r0 + 64 * i;
        uint32_t sw = (uint32_t)(row * 128 + ((ch ^ (row & 7)) << 4));
        size_t bo = (size_t)(bn0 + row) * N_ + kt + ch * 8;
        CP16(st + SB_H + sw, Bh + bo);
        CP16(st + SB_L + sw, Bl + bo);
    }
}

template <int MODE>
__global__ __launch_bounds__(512) void gemm_hmma(float* __restrict__ out) {
    extern __shared__ __align__(1024) char smem[];
    uint32_t sb = smem_u32(smem);
    int tid = threadIdx.x, lane = tid & 31, wid = tid >> 5;
    int wm = wid & 3, wn = wid >> 2;     // 4x4 warps; warp tile 32 rows x 64 cols
    int b = blockIdx.z, bm0 = blockIdx.y * 128, bn0 = blockIdx.x * 256;

    const __nv_bfloat16* Agh = g_Ah + ((size_t)b << 20);
    const __nv_bfloat16* Agl = g_Al + ((size_t)b << 20);
    const __nv_bfloat16* Bgh = (MODE == 1) ? (g_R2h + (size_t)b * TO_ * N_) : (g_Zh + (size_t)b * TO_ * N_);
    const __nv_bfloat16* Bgl = (MODE == 1) ? (g_R2l + (size_t)b * TO_ * N_) : (g_Zl + (size_t)b * TO_ * N_);

    float acc[2][8][4];
#pragma unroll
    for (int i = 0; i < 2; i++)
#pragma unroll
        for (int j = 0; j < 8; j++)
#pragma unroll
            for (int q = 0; q < 4; q++) acc[i][j][q] = 0.f;

    int a_r = (lane & 7) + ((lane >> 3) & 1) * 8;
    int a_c = lane >> 4;
    int b_r = (lane & 7) + (lane >> 4) * 8;
    int b_c = (lane >> 3) & 1;

    int rowA[2], rowB[4];
#pragma unroll
    for (int i = 0; i < 2; i++) rowA[i] = wm * 32 + 16 * i + a_r;
#pragma unroll
    for (int j2 = 0; j2 < 4; j2++) rowB[j2] = wn * 64 + 16 * j2 + b_r;

    // prefill stage 0
    fill_stage(sb, 0, bm0, bn0, Agh, Agl, Bgh, Bgl, tid);
    CP_COMMIT();

    for (int c = 0; c < 16; c++) {
        uint32_t stage = sb + (uint32_t)(c & 1) * STAGE_BYTES;
        CP_WAIT(0);
        __syncthreads();
        if (c + 1 < 16) {
            fill_stage(sb + (uint32_t)((c + 1) & 1) * STAGE_BYTES, (c + 1) * 64,
                       bm0, bn0, Agh, Agl, Bgh, Bgl, tid);
            CP_COMMIT();
        }

#pragma unroll
        for (int kk = 0; kk < 4; kk++) {
            unsigned ah[2][4], al[2][4];
#pragma unroll
            for (int i = 0; i < 2; i++) {
                uint32_t ad = stage + (uint32_t)(rowA[i] * 128 +
                    (((kk * 2 + a_c) ^ (rowA[i] & 7)) << 4));
                ldsm4(ah[i], ad);
                ldsm4(al[i], ad + SA_L);
            }
#pragma unroll
            for (int half = 0; half < 2; half++) {
                unsigned bh[2][4], bl[2][4];
#pragma unroll
                for (int jj = 0; jj < 2; jj++) {
                    int j2g = half * 2 + jj;
                    uint32_t bd = stage + SB_H + (uint32_t)(rowB[j2g] * 128 +
                        (((kk * 2 + b_c) ^ (rowB[j2g] & 7)) << 4));
                    ldsm4(bh[jj], bd);
                    ldsm4(bl[jj], bd + 32768);
                }
#pragma unroll
                for (int p = 0; p < 3; p++)
#pragma unroll
                    for (int i = 0; i < 2; i++)
#pragma unroll
                        for (int j = 0; j < 4; j++) {
                            const unsigned* pa = (p < 2) ? ah[i] : al[i];
                            const unsigned* pb = (p == 1) ? &bl[j >> 1][(j & 1) * 2]
                                                          : &bh[j >> 1][(j & 1) * 2];
                            mma16816(acc[i][half * 4 + j], pa, pb);
                        }
            }
        }
    }

    // ---------------- epilogue ----------------
    float lam = g_lam[b];
    int m0 = bm0 + wm * 32, to0 = bn0 + wn * 64;
    int rr = lane >> 2, cc = (lane & 3) * 2;

    if (MODE == 1) {
        float s4 = 4.0f / lam;
#pragma unroll
        for (int i = 0; i < 2; i++)
#pragma unroll
            for (int j = 0; j < 8; j++)
#pragma unroll
                for (int h = 0; h < 2; h++) {
                    int n = m0 + 16 * i + rr + 8 * h;
#pragma unroll
                    for (int q = 0; q < 2; q++) {
                        int to = to0 + 8 * j + cc + q;
                        size_t bi = ((size_t)b * TO_ + to) * N_ + n;
                        float r2 = __bfloat162float(g_R2h[bi]) + __bfloat162float(g_R2l[bi]);
                        float z = g_R1t[bi] + s4 * acc[i][j][2 * h + q] - 2.0f * r2;
                        __nv_bfloat16 zh = __float2bfloat16(z);
                        g_Zh[bi] = zh;
                        g_Zl[bi] = __float2bfloat16(z - __bfloat162float(zh));
                    }
                }
    } else {
        float s2 = 2.0f / lam;
        int t = to0 >> 6;   // to0 is 64-aligned: one timestep per warp tile
#pragma unroll
        for (int i = 0; i < 2; i++)
#pragma unroll
            for (int j = 0; j < 8; j++)
#pragma unroll
                for (int h = 0; h < 2; h++) {
                    int n = m0 + 16 * i + rr + 8 * h;
                    float2 v;
#pragma unroll
                    for (int q = 0; q < 2; q++) {
                        int to = to0 + 8 * j + cc + q;
                        size_t bi = ((size_t)b * TO_ + to) * N_ + n;
                        float z = __bfloat162float(g_Zh[bi]) + __bfloat162float(g_Zl[bi]);
                        float val = g_Dt[bi] + s2 * acc[i][j][2 * h + q] - z;
                        ((float*)&v)[q] = fmaxf(val, 0.f);
                    }
                    size_t oi = ((size_t)(b * T_ + t) * N_ + n) * 64 + 8 * j + cc;
                    *(float2*)&out[oi] = v;
                }
    }
}

// ---------------- launch ----------------
extern "C" void kernel_launch(void* const* d_in, const int* in_sizes, int n_in,
                              void* d_out, int out_size) {
    const float* x = nullptr;
    const float* A = nullptr;
    const float* Th = nullptr;
    for (int i = 0; i < n_in; i++) {
        if (in_sizes[i] == B_ * N_ * N_)           A  = (const float*)d_in[i];
        else if (in_sizes[i] == B_ * T_ * N_ * F_) x  = (const float*)d_in[i];
        else if (in_sizes[i] == 3 * F_ * 64)       Th = (const float*)d_in[i];
    }
    float* out = (float*)d_out;

    cudaFuncSetAttribute(gemm_hmma<1>, cudaFuncAttributeMaxDynamicSharedMemorySize, GEMM_SMEM);
    cudaFuncSetAttribute(gemm_hmma<2>, cudaFuncAttributeMaxDynamicSharedMemorySize, GEMM_SMEM);
    cudaFuncSetAttribute(feat_mma, cudaFuncAttributeMaxDynamicSharedMemorySize, FEAT_SMEM);

    lam_init_kernel<<<1, 32>>>();
    rowsum_conv_kernel<<<B_ * N_, 256>>>(A);
    feat_mma<<<(B_ * T_ * N_) / 512, 256, FEAT_SMEM>>>(x, Th);
    dim3 gg(TO_ / 256, N_ / 128, B_);
    gemm_hmma<1><<<gg, 512, GEMM_SMEM>>>(out);
    gemm_hmma<2><<<gg, 512, GEMM_SMEM>>>(out);
}

// round 14
// speedup vs baseline: 1.3763x; 1.3763x over previous
#include <cuda_runtime.h>
#include <cuda_fp16.h>
#include <cstdint>

#define B_  32
#define T_  12
#define N_  1024
#define F_  64
#define TO_ 768   // T_*O

// ---------------- device scratch (allocation-free rule) ----------------
__device__ __align__(16) __half g_Ah[(size_t)B_ * N_ * N_];
__device__ __align__(16) __half g_Al[(size_t)B_ * N_ * N_];
__device__ __align__(16) __half g_R2f[(size_t)B_ * TO_ * N_];   // fp16 MMA operand
__device__ __align__(16) __half g_Zf16[(size_t)B_ * TO_ * N_];  // fp16 MMA operand
__device__ __align__(16) float g_Zf [(size_t)B_ * TO_ * N_];    // fp32 for epilogue2
__device__ __align__(16) float g_R1p[(size_t)B_ * TO_ * N_];    // R1 - 2*R2
__device__ __align__(16) float g_Dt [(size_t)B_ * TO_ * N_];
__device__ float g_lam[B_];

// ---------------- PTX helpers ----------------
__device__ __forceinline__ uint32_t smem_u32(const void* p) {
    uint32_t a;
    asm("{ .reg .u64 t; cvta.to.shared.u64 t, %1; cvt.u32.u64 %0, t; }" : "=r"(a) : "l"(p));
    return a;
}
#define CP16(dst, src) asm volatile("cp.async.cg.shared.global [%0], [%1], 16;" :: "r"(dst), "l"(src))
#define CP_COMMIT() asm volatile("cp.async.commit_group;" ::: "memory")
#define CP_WAIT(n)  asm volatile("cp.async.wait_group %0;" :: "n"(n) : "memory")

__device__ __forceinline__ void ldsm4(unsigned* r, uint32_t addr) {
    asm volatile("ldmatrix.sync.aligned.m8n8.x4.shared.b16 {%0,%1,%2,%3}, [%4];"
                 : "=r"(r[0]), "=r"(r[1]), "=r"(r[2]), "=r"(r[3]) : "r"(addr));
}
__device__ __forceinline__ void mma16816(float* c, const unsigned* a, const unsigned* b) {
    asm volatile("mma.sync.aligned.m16n8k16.row.col.f32.f16.f16.f32 "
                 "{%0,%1,%2,%3}, {%4,%5,%6,%7}, {%8,%9}, {%0,%1,%2,%3};"
                 : "+f"(c[0]), "+f"(c[1]), "+f"(c[2]), "+f"(c[3])
                 : "r"(a[0]), "r"(a[1]), "r"(a[2]), "r"(a[3]), "r"(b[0]), "r"(b[1]));
}
__device__ __forceinline__ unsigned pack2h(float a, float b) {
    __half ha = __float2half_rn(a), hb = __float2half_rn(b);
    return ((unsigned)__half_as_ushort(hb) << 16) | __half_as_ushort(ha);
}
__device__ __forceinline__ void split_h4(float4 v, uint2& h, uint2& l) {
    __half h0 = __float2half_rn(v.x), h1 = __float2half_rn(v.y);
    __half h2 = __float2half_rn(v.z), h3 = __float2half_rn(v.w);
    float r0 = v.x - __half2float(h0), r1 = v.y - __half2float(h1);
    float r2 = v.z - __half2float(h2), r3 = v.w - __half2float(h3);
    h.x = ((unsigned)__half_as_ushort(h1) << 16) | __half_as_ushort(h0);
    h.y = ((unsigned)__half_as_ushort(h3) << 16) | __half_as_ushort(h2);
    l.x = pack2h(r0, r1);
    l.y = pack2h(r2, r3);
}

// ---------------- lambda init + rowsum + A split ----------------
__global__ void lam_init_kernel() {
    if (threadIdx.x < B_) g_lam[threadIdx.x] = 1.0f;
}

__global__ __launch_bounds__(256) void rowsum_conv_kernel(const float* __restrict__ A) {
    __shared__ float red[8];
    int row = blockIdx.x;
    int b = row >> 10;
    int t = threadIdx.x;
    const float4* ap = (const float4*)(A + (size_t)row * N_);
    float4 v = ap[t];
    uint2 h, l;
    split_h4(v, h, l);
    ((uint2*)g_Ah)[(size_t)row * 256 + t] = h;
    ((uint2*)g_Al)[(size_t)row * 256 + t] = l;

    float s = v.x + v.y + v.z + v.w;
#pragma unroll
    for (int off = 16; off > 0; off >>= 1) s += __shfl_xor_sync(0xFFFFFFFF, s, off);
    if ((t & 31) == 0) red[t >> 5] = s;
    __syncthreads();
    if (t < 8) {
        float ss = red[t];
#pragma unroll
        for (int off = 4; off > 0; off >>= 1) ss += __shfl_xor_sync(0xFF, ss, off);
        if (t == 0) atomicMax((int*)&g_lam[b], __float_as_int(ss));
    }
}

// ---------------- feat on HMMA: 2-product fp16 (x split, W single) ----------------
// c = k*64 + o; k=0 -> D, k=1/2 -> R1p = R1 - 2*R2 (fp32), R2 -> fp16
#define F_W   0
#define F_XH  24576
#define F_XL  40960
#define F_RA  57344
#define FEAT_SMEM (57344 + 192 * 132 * 4)

__global__ __launch_bounds__(256) void feat_mma(const float* __restrict__ x,
                                                const float* __restrict__ Th) {
    extern __shared__ __align__(1024) char fs[];
    uint32_t sb = smem_u32(fs);
    int tid = threadIdx.x, lane = tid & 31, wid = tid >> 5;
    int wr = wid & 3, wh = wid >> 2;

    // ---- W staging: fp32 [64 f][196 c] then fp16 [192 c][64 f] swizzled ----
    float* sWf = (float*)(fs + F_RA);
    for (int i = tid; i < 64 * 192; i += 256) {
        int f = i / 192, c = i % 192;
        int k = c >> 6, o = c & 63;
        float v;
        if (k == 0) v = Th[f * 64 + o] - Th[2 * 4096 + f * 64 + o];
        else        v = Th[k * 4096 + f * 64 + o];
        sWf[f * 196 + c] = v;
    }
    __syncthreads();
    for (int task = tid; task < 1536; task += 256) {  // 192 c-rows x 8 f-chunks
        int c = task >> 3, ch = task & 7;
        unsigned w0 = pack2h(sWf[(ch * 8 + 0) * 196 + c], sWf[(ch * 8 + 1) * 196 + c]);
        unsigned w1 = pack2h(sWf[(ch * 8 + 2) * 196 + c], sWf[(ch * 8 + 3) * 196 + c]);
        unsigned w2 = pack2h(sWf[(ch * 8 + 4) * 196 + c], sWf[(ch * 8 + 5) * 196 + c]);
        unsigned w3 = pack2h(sWf[(ch * 8 + 6) * 196 + c], sWf[(ch * 8 + 7) * 196 + c]);
        uint32_t addr = (uint32_t)(c * 128 + ((ch ^ (c & 7)) << 4));
        *(uint4*)(fs + F_W + addr) = make_uint4(w0, w1, w2, w3);
    }

    int a_r = (lane & 7) + ((lane >> 3) & 1) * 8;
    int a_c = lane >> 4;
    int b_r = (lane & 7) + (lane >> 4) * 8;
    int b_c = (lane >> 3) & 1;
    int rr = lane >> 2, cc = (lane & 3) * 2;

    for (int tile = 0; tile < 4; tile++) {
        int rows_base = blockIdx.x * 512 + tile * 128;
        __syncthreads();   // prev tile store-pass done; safe to refill x
        for (int task = tid; task < 1024; task += 256) {
            int r = task >> 3, ch = task & 7;
            const float4* px = (const float4*)(x + (size_t)(rows_base + r) * 64 + ch * 8);
            float4 v0 = px[0], v1 = px[1];
            uint2 h0, l0, h1, l1;
            split_h4(v0, h0, l0);
            split_h4(v1, h1, l1);
            uint32_t addr = (uint32_t)(r * 128 + ((ch ^ (r & 7)) << 4));
            *(uint4*)(fs + F_XH + addr) = make_uint4(h0.x, h0.y, h1.x, h1.y);
            *(uint4*)(fs + F_XL + addr) = make_uint4(l0.x, l0.y, l1.x, l1.y);
        }
        __syncthreads();

        float acc[2][12][4];
#pragma unroll
        for (int i = 0; i < 2; i++)
#pragma unroll
            for (int j = 0; j < 12; j++)
#pragma unroll
                for (int q = 0; q < 4; q++) acc[i][j][q] = 0.f;

#pragma unroll
        for (int kk = 0; kk < 4; kk++) {
            unsigned ah[2][4], al[2][4], bw[6][4];
#pragma unroll
            for (int i = 0; i < 2; i++) {
                int row = wr * 32 + 16 * i + a_r;
                int chunk = kk * 2 + a_c;
                uint32_t addr = (uint32_t)(row * 128 + ((chunk ^ (row & 7)) << 4));
                ldsm4(ah[i], sb + F_XH + addr);
                ldsm4(al[i], sb + F_XL + addr);
            }
#pragma unroll
            for (int jj = 0; jj < 6; jj++) {
                int row = wh * 96 + 16 * jj + b_r;
                int chunk = kk * 2 + b_c;
                uint32_t addr = (uint32_t)(row * 128 + ((chunk ^ (row & 7)) << 4));
                ldsm4(bw[jj], sb + F_W + addr);
            }
#pragma unroll
            for (int p = 0; p < 2; p++)
#pragma unroll
                for (int i = 0; i < 2; i++)
#pragma unroll
                    for (int j = 0; j < 12; j++) {
                        const unsigned* pa = (p == 0) ? ah[i] : al[i];
                        mma16816(acc[i][j], pa, &bw[j >> 1][(j & 1) * 2]);
                    }
        }

        // ---- transpose all 192 cols into sT, then store pass ----
        int bt = rows_base >> 10;
        int bb = bt / T_, tt = bt % T_;
        int n0 = rows_base & 1023;
        float* sT = (float*)(fs + F_RA);   // [192][132]
#pragma unroll
        for (int i = 0; i < 2; i++)
#pragma unroll
            for (int j = 0; j < 12; j++)
#pragma unroll
                for (int h = 0; h < 2; h++) {
                    int row = wr * 32 + 16 * i + rr + 8 * h;
                    int col = wh * 96 + 8 * j + cc;
                    sT[col * 132 + row]       = acc[i][j][2 * h + 0];
                    sT[(col + 1) * 132 + row] = acc[i][j][2 * h + 1];
                }
        __syncthreads();
        for (int task = tid; task < 3072; task += 256) {  // 192 cols x 16 chunks(8)
            int cl = task >> 4, ch8 = task & 15;
            int k = cl >> 6, o = cl & 63;
            const float* src = &sT[cl * 132 + ch8 * 8];
            size_t gi = ((size_t)bb * TO_ + tt * 64 + o) * N_ + n0 + ch8 * 8;
            if (k == 0) {
                *(float4*)&g_Dt[gi]     = make_float4(src[0], src[1], src[2], src[3]);
                *(float4*)&g_Dt[gi + 4] = make_float4(src[4], src[5], src[6], src[7]);
            } else if (k == 1) {
                const float* s2 = &sT[(cl + 64) * 132 + ch8 * 8];
                *(float4*)&g_R1p[gi]     = make_float4(src[0] - 2.f * s2[0], src[1] - 2.f * s2[1],
                                                       src[2] - 2.f * s2[2], src[3] - 2.f * s2[3]);
                *(float4*)&g_R1p[gi + 4] = make_float4(src[4] - 2.f * s2[4], src[5] - 2.f * s2[5],
                                                       src[6] - 2.f * s2[6], src[7] - 2.f * s2[7]);
            } else {
                unsigned p0 = pack2h(src[0], src[1]), p1 = pack2h(src[2], src[3]);
                unsigned p2 = pack2h(src[4], src[5]), p3 = pack2h(src[6], src[7]);
                *(uint4*)&g_R2f[gi] = make_uint4(p0, p1, p2, p3);
            }
        }
    }
}

// ---------------- HMMA GEMM: C[128x128] = A[b] @ Bsrc[b], 2-product fp16 ----------------
// 512 threads, 4x4 warps, 32x32 warp tiles, 4-stage BK=64 pipeline
#define SA_L 16384
#define SB_  32768
#define STAGE_BYTES 49152
#define GEMM_SMEM   (4 * STAGE_BYTES)

__device__ __forceinline__ void fill_stage(uint32_t st, int kt, int bm0, int bn0,
                                           const __half* __restrict__ Ah,
                                           const __half* __restrict__ Al,
                                           const __half* __restrict__ Bs, int tid) {
    int ch = tid & 7, r0 = tid >> 3;   // r0: 0..63
#pragma unroll
    for (int i = 0; i < 2; i++) {
        int row = r0 + 64 * i;
        uint32_t sw = (uint32_t)(row * 128 + ((ch ^ (row & 7)) << 4));
        size_t ao = (size_t)(bm0 + row) * N_ + kt + ch * 8;
        size_t bo = (size_t)(bn0 + row) * N_ + kt + ch * 8;
        CP16(st + sw,        Ah + ao);
        CP16(st + SA_L + sw, Al + ao);
        CP16(st + SB_ + sw,  Bs + bo);
    }
}

template <int MODE>
__global__ __launch_bounds__(512) void gemm_hmma(float* __restrict__ out) {
    extern __shared__ __align__(1024) char smem[];
    uint32_t sb = smem_u32(smem);
    int tid = threadIdx.x, lane = tid & 31, wid = tid >> 5;
    int wm = wid & 3, wn = wid >> 2;     // 4x4 warps, 32x32 tiles
    int b = blockIdx.z, bm0 = blockIdx.y * 128, bn0 = blockIdx.x * 128;

    const __half* Agh = g_Ah + ((size_t)b << 20);
    const __half* Agl = g_Al + ((size_t)b << 20);
    const __half* Bgs = (MODE == 1) ? (g_R2f + (size_t)b * TO_ * N_) : (g_Zf16 + (size_t)b * TO_ * N_);

    float acc[2][4][4];
#pragma unroll
    for (int i = 0; i < 2; i++)
#pragma unroll
        for (int j = 0; j < 4; j++)
#pragma unroll
            for (int q = 0; q < 4; q++) acc[i][j][q] = 0.f;

    int a_r = (lane & 7) + ((lane >> 3) & 1) * 8;
    int a_c = lane >> 4;
    int b_r = (lane & 7) + (lane >> 4) * 8;
    int b_c = (lane >> 3) & 1;

    int rowA[2], rowB[2];
#pragma unroll
    for (int i = 0; i < 2; i++) rowA[i] = wm * 32 + 16 * i + a_r;
#pragma unroll
    for (int j2 = 0; j2 < 2; j2++) rowB[j2] = wn * 32 + 16 * j2 + b_r;

#pragma unroll
    for (int c = 0; c < 3; c++) {
        fill_stage(sb + c * STAGE_BYTES, c * 64, bm0, bn0, Agh, Agl, Bgs, tid);
        CP_COMMIT();
    }

    for (int c = 0; c < 16; c++) {
        uint32_t stage = sb + (uint32_t)(c & 3) * STAGE_BYTES;
        if (c <= 13)      CP_WAIT(2);
        else if (c == 14) CP_WAIT(1);
        else              CP_WAIT(0);
        __syncthreads();

#pragma unroll
        for (int kk = 0; kk < 4; kk++) {
            unsigned ah[2][4], al[2][4], bf[2][4];
#pragma unroll
            for (int i = 0; i < 2; i++) {
                uint32_t ad = stage + (uint32_t)(rowA[i] * 128 +
                    (((kk * 2 + a_c) ^ (rowA[i] & 7)) << 4));
                ldsm4(ah[i], ad);
                ldsm4(al[i], ad + SA_L);
            }
#pragma unroll
            for (int j2 = 0; j2 < 2; j2++) {
                uint32_t bd = stage + SB_ + (uint32_t)(rowB[j2] * 128 +
                    (((kk * 2 + b_c) ^ (rowB[j2] & 7)) << 4));
                ldsm4(bf[j2], bd);
            }
#pragma unroll
            for (int p = 0; p < 2; p++)
#pragma unroll
                for (int i = 0; i < 2; i++)
#pragma unroll
                    for (int j = 0; j < 4; j++) {
                        const unsigned* pa = (p == 0) ? ah[i] : al[i];
                        mma16816(acc[i][j], pa, &bf[j >> 1][(j & 1) * 2]);
                    }
        }

        // 4 stages: fill target (c+3)&3 was consumed at c-1; top barrier protects it
        if (c + 3 < 16) {
            fill_stage(sb + (uint32_t)((c + 3) & 3) * STAGE_BYTES, (c + 3) * 64,
                       bm0, bn0, Agh, Agl, Bgs, tid);
            CP_COMMIT();
        }
    }

    // ---------------- epilogue ----------------
    float lam = g_lam[b];
    int m0 = bm0 + wm * 32, to0 = bn0 + wn * 32;
    int rr = lane >> 2, cc = (lane & 3) * 2;

    if (MODE == 1) {
        float s4 = 4.0f / lam;
#pragma unroll
        for (int i = 0; i < 2; i++)
#pragma unroll
            for (int j = 0; j < 4; j++)
#pragma unroll
                for (int h = 0; h < 2; h++) {
                    int n = m0 + 16 * i + rr + 8 * h;
#pragma unroll
                    for (int q = 0; q < 2; q++) {
                        int to = to0 + 8 * j + cc + q;
                        size_t bi = ((size_t)b * TO_ + to) * N_ + n;
                        float z = g_R1p[bi] + s4 * acc[i][j][2 * h + q];
                        g_Zf[bi] = z;
                        g_Zf16[bi] = __float2half_rn(z);
                    }
                }
    } else {
        float s2 = 2.0f / lam;
        int t = to0 >> 6;
        int o0 = to0 & 63;
#pragma unroll
        for (int i = 0; i < 2; i++)
#pragma unroll
            for (int j = 0; j < 4; j++)
#pragma unroll
                for (int h = 0; h < 2; h++) {
                    int n = m0 + 16 * i + rr + 8 * h;
                    float2 v;
#pragma unroll
                    for (int q = 0; q < 2; q++) {
                        int to = to0 + 8 * j + cc + q;
                        size_t bi = ((size_t)b * TO_ + to) * N_ + n;
                        float val = g_Dt[bi] + s2 * acc[i][j][2 * h + q] - g_Zf[bi];
                        ((float*)&v)[q] = fmaxf(val, 0.f);
                    }
                    size_t oi = ((size_t)(b * T_ + t) * N_ + n) * 64 + o0 + 8 * j + cc;
                    *(float2*)&out[oi] = v;
                }
    }
}

// ---------------- launch ----------------
extern "C" void kernel_launch(void* const* d_in, const int* in_sizes, int n_in,
                              void* d_out, int out_size) {
    const float* x = nullptr;
    const float* A = nullptr;
    const float* Th = nullptr;
    for (int i = 0; i < n_in; i++) {
        if (in_sizes[i] == B_ * N_ * N_)           A  = (const float*)d_in[i];
        else if (in_sizes[i] == B_ * T_ * N_ * F_) x  = (const float*)d_in[i];
        else if (in_sizes[i] == 3 * F_ * 64)       Th = (const float*)d_in[i];
    }
    float* out = (float*)d_out;

    cudaFuncSetAttribute(gemm_hmma<1>, cudaFuncAttributeMaxDynamicSharedMemorySize, GEMM_SMEM);
    cudaFuncSetAttribute(gemm_hmma<2>, cudaFuncAttributeMaxDynamicSharedMemorySize, GEMM_SMEM);
    cudaFuncSetAttribute(feat_mma, cudaFuncAttributeMaxDynamicSharedMemorySize, FEAT_SMEM);

    lam_init_kernel<<<1, 32>>>();
    rowsum_conv_kernel<<<B_ * N_, 256>>>(A);
    feat_mma<<<(B_ * T_ * N_) / 512, 256, FEAT_SMEM>>>(x, Th);
    dim3 gg(TO_ / 128, N_ / 128, B_);
    gemm_hmma<1><<<gg, 512, GEMM_SMEM>>>(out);
    gemm_hmma<2><<<gg, 512, GEMM_SMEM>>>(out);
}

// round 16
// speedup vs baseline: 1.5630x; 1.1357x over previous
#include <cuda_runtime.h>
#include <cuda_fp16.h>
#include <cstdint>

#define B_  32
#define T_  12
#define N_  1024
#define F_  64
#define TO_ 768   // T_*O

// ---------------- device scratch (allocation-free rule) ----------------
__device__ __align__(16) __half g_Ah[(size_t)B_ * N_ * N_];
__device__ __align__(16) __half g_Al[(size_t)B_ * N_ * N_];
__device__ __align__(16) __half g_R2f[(size_t)B_ * TO_ * N_];   // fp16 MMA operand
__device__ __align__(16) __half g_Zf16[(size_t)B_ * TO_ * N_];  // fp16 MMA operand
__device__ __align__(16) float g_Zf [(size_t)B_ * TO_ * N_];    // fp32 for epilogue2
__device__ __align__(16) float g_R1p[(size_t)B_ * TO_ * N_];    // R1 - 2*R2
__device__ __align__(16) float g_Dt [(size_t)B_ * TO_ * N_];
__device__ float g_lam[B_];

// ---------------- PTX helpers ----------------
__device__ __forceinline__ uint32_t smem_u32(const void* p) {
    uint32_t a;
    asm("{ .reg .u64 t; cvta.to.shared.u64 t, %1; cvt.u32.u64 %0, t; }" : "=r"(a) : "l"(p));
    return a;
}
#define CP16(dst, src) asm volatile("cp.async.cg.shared.global [%0], [%1], 16;" :: "r"(dst), "l"(src))
#define CP_COMMIT() asm volatile("cp.async.commit_group;" ::: "memory")
#define CP_WAIT(n)  asm volatile("cp.async.wait_group %0;" :: "n"(n) : "memory")

__device__ __forceinline__ void ldsm4(unsigned* r, uint32_t addr) {
    asm volatile("ldmatrix.sync.aligned.m8n8.x4.shared.b16 {%0,%1,%2,%3}, [%4];"
                 : "=r"(r[0]), "=r"(r[1]), "=r"(r[2]), "=r"(r[3]) : "r"(addr));
}
__device__ __forceinline__ void mma16816(float* c, const unsigned* a, const unsigned* b) {
    asm volatile("mma.sync.aligned.m16n8k16.row.col.f32.f16.f16.f32 "
                 "{%0,%1,%2,%3}, {%4,%5,%6,%7}, {%8,%9}, {%0,%1,%2,%3};"
                 : "+f"(c[0]), "+f"(c[1]), "+f"(c[2]), "+f"(c[3])
                 : "r"(a[0]), "r"(a[1]), "r"(a[2]), "r"(a[3]), "r"(b[0]), "r"(b[1]));
}
__device__ __forceinline__ unsigned pack2h(float a, float b) {
    __half ha = __float2half_rn(a), hb = __float2half_rn(b);
    return ((unsigned)__half_as_ushort(hb) << 16) | __half_as_ushort(ha);
}
__device__ __forceinline__ void split_h4(float4 v, uint2& h, uint2& l) {
    __half h0 = __float2half_rn(v.x), h1 = __float2half_rn(v.y);
    __half h2 = __float2half_rn(v.z), h3 = __float2half_rn(v.w);
    float r0 = v.x - __half2float(h0), r1 = v.y - __half2float(h1);
    float r2 = v.z - __half2float(h2), r3 = v.w - __half2float(h3);
    h.x = ((unsigned)__half_as_ushort(h1) << 16) | __half_as_ushort(h0);
    h.y = ((unsigned)__half_as_ushort(h3) << 16) | __half_as_ushort(h2);
    l.x = pack2h(r0, r1);
    l.y = pack2h(r2, r3);
}

// ---------------- lambda init + rowsum + A split ----------------
__global__ void lam_init_kernel() {
    if (threadIdx.x < B_) g_lam[threadIdx.x] = 1.0f;
}

__global__ __launch_bounds__(256) void rowsum_conv_kernel(const float* __restrict__ A) {
    __shared__ float red[8];
    int row = blockIdx.x;
    int b = row >> 10;
    int t = threadIdx.x;
    const float4* ap = (const float4*)(A + (size_t)row * N_);
    float4 v = ap[t];
    uint2 h, l;
    split_h4(v, h, l);
    ((uint2*)g_Ah)[(size_t)row * 256 + t] = h;
    ((uint2*)g_Al)[(size_t)row * 256 + t] = l;

    float s = v.x + v.y + v.z + v.w;
#pragma unroll
    for (int off = 16; off > 0; off >>= 1) s += __shfl_xor_sync(0xFFFFFFFF, s, off);
    if ((t & 31) == 0) red[t >> 5] = s;
    __syncthreads();
    if (t < 8) {
        float ss = red[t];
#pragma unroll
        for (int off = 4; off > 0; off >>= 1) ss += __shfl_xor_sync(0xFF, ss, off);
        if (t == 0) atomicMax((int*)&g_lam[b], __float_as_int(ss));
    }
}

// ---------------- feat on HMMA: 2-product fp16 (x split, W single) ----------------
#define F_W   0
#define F_XH  24576
#define F_XL  40960
#define F_RA  57344
#define FEAT_SMEM (57344 + 192 * 132 * 4)

__global__ __launch_bounds__(256) void feat_mma(const float* __restrict__ x,
                                                const float* __restrict__ Th) {
    extern __shared__ __align__(1024) char fs[];
    uint32_t sb = smem_u32(fs);
    int tid = threadIdx.x, lane = tid & 31, wid = tid >> 5;
    int wr = wid & 3, wh = wid >> 2;

    float* sWf = (float*)(fs + F_RA);
    for (int i = tid; i < 64 * 192; i += 256) {
        int f = i / 192, c = i % 192;
        int k = c >> 6, o = c & 63;
        float v;
        if (k == 0) v = Th[f * 64 + o] - Th[2 * 4096 + f * 64 + o];
        else        v = Th[k * 4096 + f * 64 + o];
        sWf[f * 196 + c] = v;
    }
    __syncthreads();
    for (int task = tid; task < 1536; task += 256) {
        int c = task >> 3, ch = task & 7;
        unsigned w0 = pack2h(sWf[(ch * 8 + 0) * 196 + c], sWf[(ch * 8 + 1) * 196 + c]);
        unsigned w1 = pack2h(sWf[(ch * 8 + 2) * 196 + c], sWf[(ch * 8 + 3) * 196 + c]);
        unsigned w2 = pack2h(sWf[(ch * 8 + 4) * 196 + c], sWf[(ch * 8 + 5) * 196 + c]);
        unsigned w3 = pack2h(sWf[(ch * 8 + 6) * 196 + c], sWf[(ch * 8 + 7) * 196 + c]);
        uint32_t addr = (uint32_t)(c * 128 + ((ch ^ (c & 7)) << 4));
        *(uint4*)(fs + F_W + addr) = make_uint4(w0, w1, w2, w3);
    }

    int a_r = (lane & 7) + ((lane >> 3) & 1) * 8;
    int a_c = lane >> 4;
    int b_r = (lane & 7) + (lane >> 4) * 8;
    int b_c = (lane >> 3) & 1;
    int rr = lane >> 2, cc = (lane & 3) * 2;

    for (int tile = 0; tile < 4; tile++) {
        int rows_base = blockIdx.x * 512 + tile * 128;
        __syncthreads();
        for (int task = tid; task < 1024; task += 256) {
            int r = task >> 3, ch = task & 7;
            const float4* px = (const float4*)(x + (size_t)(rows_base + r) * 64 + ch * 8);
            float4 v0 = px[0], v1 = px[1];
            uint2 h0, l0, h1, l1;
            split_h4(v0, h0, l0);
            split_h4(v1, h1, l1);
            uint32_t addr = (uint32_t)(r * 128 + ((ch ^ (r & 7)) << 4));
            *(uint4*)(fs + F_XH + addr) = make_uint4(h0.x, h0.y, h1.x, h1.y);
            *(uint4*)(fs + F_XL + addr) = make_uint4(l0.x, l0.y, l1.x, l1.y);
        }
        __syncthreads();

        float acc[2][12][4];
#pragma unroll
        for (int i = 0; i < 2; i++)
#pragma unroll
            for (int j = 0; j < 12; j++)
#pragma unroll
                for (int q = 0; q < 4; q++) acc[i][j][q] = 0.f;

#pragma unroll
        for (int kk = 0; kk < 4; kk++) {
            unsigned ah[2][4], al[2][4], bw[6][4];
#pragma unroll
            for (int i = 0; i < 2; i++) {
                int row = wr * 32 + 16 * i + a_r;
                int chunk = kk * 2 + a_c;
                uint32_t addr = (uint32_t)(row * 128 + ((chunk ^ (row & 7)) << 4));
                ldsm4(ah[i], sb + F_XH + addr);
                ldsm4(al[i], sb + F_XL + addr);
            }
#pragma unroll
            for (int jj = 0; jj < 6; jj++) {
                int row = wh * 96 + 16 * jj + b_r;
                int chunk = kk * 2 + b_c;
                uint32_t addr = (uint32_t)(row * 128 + ((chunk ^ (row & 7)) << 4));
                ldsm4(bw[jj], sb + F_W + addr);
            }
#pragma unroll
            for (int p = 0; p < 2; p++)
#pragma unroll
                for (int i = 0; i < 2; i++)
#pragma unroll
                    for (int j = 0; j < 12; j++) {
                        const unsigned* pa = (p == 0) ? ah[i] : al[i];
                        mma16816(acc[i][j], pa, &bw[j >> 1][(j & 1) * 2]);
                    }
        }

        int bt = rows_base >> 10;
        int bb = bt / T_, tt = bt % T_;
        int n0 = rows_base & 1023;
        float* sT = (float*)(fs + F_RA);   // [192][132]
#pragma unroll
        for (int i = 0; i < 2; i++)
#pragma unroll
            for (int j = 0; j < 12; j++)
#pragma unroll
                for (int h = 0; h < 2; h++) {
                    int row = wr * 32 + 16 * i + rr + 8 * h;
                    int col = wh * 96 + 8 * j + cc;
                    sT[col * 132 + row]       = acc[i][j][2 * h + 0];
                    sT[(col + 1) * 132 + row] = acc[i][j][2 * h + 1];
                }
        __syncthreads();
        for (int task = tid; task < 3072; task += 256) {
            int cl = task >> 4, ch8 = task & 15;
            int k = cl >> 6, o = cl & 63;
            const float* src = &sT[cl * 132 + ch8 * 8];
            size_t gi = ((size_t)bb * TO_ + tt * 64 + o) * N_ + n0 + ch8 * 8;
            if (k == 0) {
                *(float4*)&g_Dt[gi]     = make_float4(src[0], src[1], src[2], src[3]);
                *(float4*)&g_Dt[gi + 4] = make_float4(src[4], src[5], src[6], src[7]);
            } else if (k == 1) {
                const float* s2 = &sT[(cl + 64) * 132 + ch8 * 8];
                *(float4*)&g_R1p[gi]     = make_float4(src[0] - 2.f * s2[0], src[1] - 2.f * s2[1],
                                                       src[2] - 2.f * s2[2], src[3] - 2.f * s2[3]);
                *(float4*)&g_R1p[gi + 4] = make_float4(src[4] - 2.f * s2[4], src[5] - 2.f * s2[5],
                                                       src[6] - 2.f * s2[6], src[7] - 2.f * s2[7]);
            } else {
                unsigned p0 = pack2h(src[0], src[1]), p1 = pack2h(src[2], src[3]);
                unsigned p2 = pack2h(src[4], src[5]), p3 = pack2h(src[6], src[7]);
                *(uint4*)&g_R2f[gi] = make_uint4(p0, p1, p2, p3);
            }
        }
    }
}

// ---------------- HMMA GEMM: C[64x128] = A[b] @ Bsrc[b], 2-product fp16 ----------------
// 256 threads, 2x4 warps, 32x32 warp tiles, 3-stage BK=64, 96KB smem -> 2 CTAs/SM
#define SA_L 8192
#define SB_  16384
#define STAGE_BYTES 32768
#define GEMM_SMEM   (3 * STAGE_BYTES)

__device__ __forceinline__ void fill_stage(uint32_t st, int kt, int bm0, int bn0,
                                           const __half* __restrict__ Ah,
                                           const __half* __restrict__ Al,
                                           const __half* __restrict__ Bs, int tid) {
    int ch = tid & 7, r0 = tid >> 3;   // r0: 0..31
    // A: 64 rows (Ah + Al)
#pragma unroll
    for (int i = 0; i < 2; i++) {
        int row = r0 + 32 * i;
        uint32_t sw = (uint32_t)(row * 128 + ((ch ^ (row & 7)) << 4));
        size_t ao = (size_t)(bm0 + row) * N_ + kt + ch * 8;
        CP16(st + sw,        Ah + ao);
        CP16(st + SA_L + sw, Al + ao);
    }
    // B: 128 rows
#pragma unroll
    for (int i = 0; i < 4; i++) {
        int row = r0 + 32 * i;
        uint32_t sw = (uint32_t)(row * 128 + ((ch ^ (row & 7)) << 4));
        size_t bo = (size_t)(bn0 + row) * N_ + kt + ch * 8;
        CP16(st + SB_ + sw, Bs + bo);
    }
}

template <int MODE>
__global__ __launch_bounds__(256) void gemm_hmma(float* __restrict__ out) {
    extern __shared__ __align__(1024) char smem[];
    uint32_t sb = smem_u32(smem);
    int tid = threadIdx.x, lane = tid & 31, wid = tid >> 5;
    int wm = wid & 1, wn = wid >> 1;     // 2x4 warps, 32x32 tiles
    int b = blockIdx.z, bm0 = blockIdx.y * 64, bn0 = blockIdx.x * 128;

    const __half* Agh = g_Ah + ((size_t)b << 20);
    const __half* Agl = g_Al + ((size_t)b << 20);
    const __half* Bgs = (MODE == 1) ? (g_R2f + (size_t)b * TO_ * N_) : (g_Zf16 + (size_t)b * TO_ * N_);

    float acc[2][4][4];
#pragma unroll
    for (int i = 0; i < 2; i++)
#pragma unroll
        for (int j = 0; j < 4; j++)
#pragma unroll
            for (int q = 0; q < 4; q++) acc[i][j][q] = 0.f;

    int a_r = (lane & 7) + ((lane >> 3) & 1) * 8;
    int a_c = lane >> 4;
    int b_r = (lane & 7) + (lane >> 4) * 8;
    int b_c = (lane >> 3) & 1;

    int rowA[2], rowB[2];
#pragma unroll
    for (int i = 0; i < 2; i++) rowA[i] = wm * 32 + 16 * i + a_r;
#pragma unroll
    for (int j2 = 0; j2 < 2; j2++) rowB[j2] = wn * 32 + 16 * j2 + b_r;

#pragma unroll
    for (int c = 0; c < 3; c++) {
        fill_stage(sb + c * STAGE_BYTES, c * 64, bm0, bn0, Agh, Agl, Bgs, tid);
        CP_COMMIT();
    }

    for (int c = 0; c < 16; c++) {
        uint32_t stage = sb + (uint32_t)(c % 3) * STAGE_BYTES;
        if (c <= 13)      CP_WAIT(2);
        else if (c == 14) CP_WAIT(1);
        else              CP_WAIT(0);
        __syncthreads();

#pragma unroll
        for (int kk = 0; kk < 4; kk++) {
            unsigned ah[2][4], al[2][4], bf[2][4];
#pragma unroll
            for (int i = 0; i < 2; i++) {
                uint32_t ad = stage + (uint32_t)(rowA[i] * 128 +
                    (((kk * 2 + a_c) ^ (rowA[i] & 7)) << 4));
                ldsm4(ah[i], ad);
                ldsm4(al[i], ad + SA_L);
            }
#pragma unroll
            for (int j2 = 0; j2 < 2; j2++) {
                uint32_t bd = stage + SB_ + (uint32_t)(rowB[j2] * 128 +
                    (((kk * 2 + b_c) ^ (rowB[j2] & 7)) << 4));
                ldsm4(bf[j2], bd);
            }
#pragma unroll
            for (int p = 0; p < 2; p++)
#pragma unroll
                for (int i = 0; i < 2; i++)
#pragma unroll
                    for (int j = 0; j < 4; j++) {
                        const unsigned* pa = (p == 0) ? ah[i] : al[i];
                        mma16816(acc[i][j], pa, &bf[j >> 1][(j & 1) * 2]);
                    }
        }

        // refill the just-consumed buffer (3-stage ring) for k-chunk c+3
        if (c + 3 < 16) {
            __syncthreads();
            fill_stage(stage, (c + 3) * 64, bm0, bn0, Agh, Agl, Bgs, tid);
            CP_COMMIT();
        }
    }

    // ---------------- epilogue ----------------
    float lam = g_lam[b];
    int m0 = bm0 + wm * 32, to0 = bn0 + wn * 32;
    int rr = lane >> 2, cc = (lane & 3) * 2;

    if (MODE == 1) {
        float s4 = 4.0f / lam;
#pragma unroll
        for (int i = 0; i < 2; i++)
#pragma unroll
            for (int j = 0; j < 4; j++)
#pragma unroll
                for (int h = 0; h < 2; h++) {
                    int n = m0 + 16 * i + rr + 8 * h;
#pragma unroll
                    for (int q = 0; q < 2; q++) {
                        int to = to0 + 8 * j + cc + q;
                        size_t bi = ((size_t)b * TO_ + to) * N_ + n;
                        float z = g_R1p[bi] + s4 * acc[i][j][2 * h + q];
                        g_Zf[bi] = z;
                        g_Zf16[bi] = __float2half_rn(z);
                    }
                }
    } else {
        float s2 = 2.0f / lam;
        int t = to0 >> 6;
        int o0 = to0 & 63;
#pragma unroll
        for (int i = 0; i < 2; i++)
#pragma unroll
            for (int j = 0; j < 4; j++)
#pragma unroll
                for (int h = 0; h < 2; h++) {
                    int n = m0 + 16 * i + rr + 8 * h;
                    float2 v;
#pragma unroll
                    for (int q = 0; q < 2; q++) {
                        int to = to0 + 8 * j + cc + q;
                        size_t bi = ((size_t)b * TO_ + to) * N_ + n;
                        float val = g_Dt[bi] + s2 * acc[i][j][2 * h + q] - g_Zf[bi];
                        ((float*)&v)[q] = fmaxf(val, 0.f);
                    }
                    size_t oi = ((size_t)(b * T_ + t) * N_ + n) * 64 + o0 + 8 * j + cc;
                    *(float2*)&out[oi] = v;
                }
    }
}

// ---------------- launch ----------------
extern "C" void kernel_launch(void* const* d_in, const int* in_sizes, int n_in,
                              void* d_out, int out_size) {
    const float* x = nullptr;
    const float* A = nullptr;
    const float* Th = nullptr;
    for (int i = 0; i < n_in; i++) {
        if (in_sizes[i] == B_ * N_ * N_)           A  = (const float*)d_in[i];
        else if (in_sizes[i] == B_ * T_ * N_ * F_) x  = (const float*)d_in[i];
        else if (in_sizes[i] == 3 * F_ * 64)       Th = (const float*)d_in[i];
    }
    float* out = (float*)d_out;

    cudaFuncSetAttribute(gemm_hmma<1>, cudaFuncAttributeMaxDynamicSharedMemorySize, GEMM_SMEM);
    cudaFuncSetAttribute(gemm_hmma<2>, cudaFuncAttributeMaxDynamicSharedMemorySize, GEMM_SMEM);
    cudaFuncSetAttribute(feat_mma, cudaFuncAttributeMaxDynamicSharedMemorySize, FEAT_SMEM);

    lam_init_kernel<<<1, 32>>>();
    rowsum_conv_kernel<<<B_ * N_, 256>>>(A);
    feat_mma<<<(B_ * T_ * N_) / 512, 256, FEAT_SMEM>>>(x, Th);
    dim3 gg(TO_ / 128, N_ / 64, B_);
    gemm_hmma<1><<<gg, 256, GEMM_SMEM>>>(out);
    gemm_hmma<2><<<gg, 256, GEMM_SMEM>>>(out);
}

// round 17
// speedup vs baseline: 2.0190x; 1.2917x over previous
#include <cuda_runtime.h>
#include <cuda_fp16.h>
#include <cstdint>

#define B_  32
#define T_  12
#define N_  1024
#define F_  64
#define TO_ 768   // T_*O

// ---------------- device scratch (allocation-free rule) ----------------
__device__ __align__(16) __half g_Af[(size_t)B_ * N_ * N_];     // fp16(A)
__device__ __align__(16) __half g_R2f[(size_t)B_ * TO_ * N_];   // fp16 MMA operand
__device__ __align__(16) __half g_Zf16[(size_t)B_ * TO_ * N_];  // fp16 MMA operand
__device__ __align__(16) float g_Zf [(size_t)B_ * TO_ * N_];    // fp32 for epilogue2
__device__ __align__(16) float g_R1p[(size_t)B_ * TO_ * N_];    // R1 - 2*R2
__device__ __align__(16) float g_Dt [(size_t)B_ * TO_ * N_];
__device__ float g_lam[B_];

// ---------------- PTX helpers ----------------
__device__ __forceinline__ uint32_t smem_u32(const void* p) {
    uint32_t a;
    asm("{ .reg .u64 t; cvta.to.shared.u64 t, %1; cvt.u32.u64 %0, t; }" : "=r"(a) : "l"(p));
    return a;
}
#define CP16(dst, src) asm volatile("cp.async.cg.shared.global [%0], [%1], 16;" :: "r"(dst), "l"(src))
#define CP_COMMIT() asm volatile("cp.async.commit_group;" ::: "memory")
#define CP_WAIT(n)  asm volatile("cp.async.wait_group %0;" :: "n"(n) : "memory")

__device__ __forceinline__ void ldsm4(unsigned* r, uint32_t addr) {
    asm volatile("ldmatrix.sync.aligned.m8n8.x4.shared.b16 {%0,%1,%2,%3}, [%4];"
                 : "=r"(r[0]), "=r"(r[1]), "=r"(r[2]), "=r"(r[3]) : "r"(addr));
}
__device__ __forceinline__ void mma16816(float* c, const unsigned* a, const unsigned* b) {
    asm volatile("mma.sync.aligned.m16n8k16.row.col.f32.f16.f16.f32 "
                 "{%0,%1,%2,%3}, {%4,%5,%6,%7}, {%8,%9}, {%0,%1,%2,%3};"
                 : "+f"(c[0]), "+f"(c[1]), "+f"(c[2]), "+f"(c[3])
                 : "r"(a[0]), "r"(a[1]), "r"(a[2]), "r"(a[3]), "r"(b[0]), "r"(b[1]));
}
__device__ __forceinline__ unsigned pack2h(float a, float b) {
    __half ha = __float2half_rn(a), hb = __float2half_rn(b);
    return ((unsigned)__half_as_ushort(hb) << 16) | __half_as_ushort(ha);
}
__device__ __forceinline__ void split_h4(float4 v, uint2& h, uint2& l) {
    __half h0 = __float2half_rn(v.x), h1 = __float2half_rn(v.y);
    __half h2 = __float2half_rn(v.z), h3 = __float2half_rn(v.w);
    float r0 = v.x - __half2float(h0), r1 = v.y - __half2float(h1);
    float r2 = v.z - __half2float(h2), r3 = v.w - __half2float(h3);
    h.x = ((unsigned)__half_as_ushort(h1) << 16) | __half_as_ushort(h0);
    h.y = ((unsigned)__half_as_ushort(h3) << 16) | __half_as_ushort(h2);
    l.x = pack2h(r0, r1);
    l.y = pack2h(r2, r3);
}

// ---------------- lambda init + rowsum + A convert ----------------
__global__ void lam_init_kernel() {
    if (threadIdx.x < B_) g_lam[threadIdx.x] = 1.0f;
}

__global__ __launch_bounds__(256) void rowsum_conv_kernel(const float* __restrict__ A) {
    __shared__ float red[8];
    int row = blockIdx.x;
    int b = row >> 10;
    int t = threadIdx.x;
    const float4* ap = (const float4*)(A + (size_t)row * N_);
    float4 v = ap[t];
    unsigned h01 = pack2h(v.x, v.y);
    unsigned h23 = pack2h(v.z, v.w);
    ((uint2*)g_Af)[(size_t)row * 256 + t] = make_uint2(h01, h23);

    float s = v.x + v.y + v.z + v.w;
#pragma unroll
    for (int off = 16; off > 0; off >>= 1) s += __shfl_xor_sync(0xFFFFFFFF, s, off);
    if ((t & 31) == 0) red[t >> 5] = s;
    __syncthreads();
    if (t < 8) {
        float ss = red[t];
#pragma unroll
        for (int off = 4; off > 0; off >>= 1) ss += __shfl_xor_sync(0xFF, ss, off);
        if (t == 0) atomicMax((int*)&g_lam[b], __float_as_int(ss));
    }
}

// ---------------- feat on HMMA: 2-product fp16 (x split, W single) ----------------
#define F_W   0
#define F_XH  24576
#define F_XL  40960
#define F_RA  57344
#define FEAT_SMEM (57344 + 192 * 132 * 4)

__global__ __launch_bounds__(256) void feat_mma(const float* __restrict__ x,
                                                const float* __restrict__ Th) {
    extern __shared__ __align__(1024) char fs[];
    uint32_t sb = smem_u32(fs);
    int tid = threadIdx.x, lane = tid & 31, wid = tid >> 5;
    int wr = wid & 3, wh = wid >> 2;

    float* sWf = (float*)(fs + F_RA);
    for (int i = tid; i < 64 * 192; i += 256) {
        int f = i / 192, c = i % 192;
        int k = c >> 6, o = c & 63;
        float v;
        if (k == 0) v = Th[f * 64 + o] - Th[2 * 4096 + f * 64 + o];
        else        v = Th[k * 4096 + f * 64 + o];
        sWf[f * 196 + c] = v;
    }
    __syncthreads();
    for (int task = tid; task < 1536; task += 256) {
        int c = task >> 3, ch = task & 7;
        unsigned w0 = pack2h(sWf[(ch * 8 + 0) * 196 + c], sWf[(ch * 8 + 1) * 196 + c]);
        unsigned w1 = pack2h(sWf[(ch * 8 + 2) * 196 + c], sWf[(ch * 8 + 3) * 196 + c]);
        unsigned w2 = pack2h(sWf[(ch * 8 + 4) * 196 + c], sWf[(ch * 8 + 5) * 196 + c]);
        unsigned w3 = pack2h(sWf[(ch * 8 + 6) * 196 + c], sWf[(ch * 8 + 7) * 196 + c]);
        uint32_t addr = (uint32_t)(c * 128 + ((ch ^ (c & 7)) << 4));
        *(uint4*)(fs + F_W + addr) = make_uint4(w0, w1, w2, w3);
    }

    int a_r = (lane & 7) + ((lane >> 3) & 1) * 8;
    int a_c = lane >> 4;
    int b_r = (lane & 7) + (lane >> 4) * 8;
    int b_c = (lane >> 3) & 1;
    int rr = lane >> 2, cc = (lane & 3) * 2;

    for (int tile = 0; tile < 4; tile++) {
        int rows_base = blockIdx.x * 512 + tile * 128;
        __syncthreads();
        for (int task = tid; task < 1024; task += 256) {
            int r = task >> 3, ch = task & 7;
            const float4* px = (const float4*)(x + (size_t)(rows_base + r) * 64 + ch * 8);
            float4 v0 = px[0], v1 = px[1];
            uint2 h0, l0, h1, l1;
            split_h4(v0, h0, l0);
            split_h4(v1, h1, l1);
            uint32_t addr = (uint32_t)(r * 128 + ((ch ^ (r & 7)) << 4));
            *(uint4*)(fs + F_XH + addr) = make_uint4(h0.x, h0.y, h1.x, h1.y);
            *(uint4*)(fs + F_XL + addr) = make_uint4(l0.x, l0.y, l1.x, l1.y);
        }
        __syncthreads();

        float acc[2][12][4];
#pragma unroll
        for (int i = 0; i < 2; i++)
#pragma unroll
            for (int j = 0; j < 12; j++)
#pragma unroll
                for (int q = 0; q < 4; q++) acc[i][j][q] = 0.f;

#pragma unroll
        for (int kk = 0; kk < 4; kk++) {
            unsigned ah[2][4], al[2][4], bw[6][4];
#pragma unroll
            for (int i = 0; i < 2; i++) {
                int row = wr * 32 + 16 * i + a_r;
                int chunk = kk * 2 + a_c;
                uint32_t addr = (uint32_t)(row * 128 + ((chunk ^ (row & 7)) << 4));
                ldsm4(ah[i], sb + F_XH + addr);
                ldsm4(al[i], sb + F_XL + addr);
            }
#pragma unroll
            for (int jj = 0; jj < 6; jj++) {
                int row = wh * 96 + 16 * jj + b_r;
                int chunk = kk * 2 + b_c;
                uint32_t addr = (uint32_t)(row * 128 + ((chunk ^ (row & 7)) << 4));
                ldsm4(bw[jj], sb + F_W + addr);
            }
#pragma unroll
            for (int p = 0; p < 2; p++)
#pragma unroll
                for (int i = 0; i < 2; i++)
#pragma unroll
                    for (int j = 0; j < 12; j++) {
                        const unsigned* pa = (p == 0) ? ah[i] : al[i];
                        mma16816(acc[i][j], pa, &bw[j >> 1][(j & 1) * 2]);
                    }
        }

        int bt = rows_base >> 10;
        int bb = bt / T_, tt = bt % T_;
        int n0 = rows_base & 1023;
        float* sT = (float*)(fs + F_RA);   // [192][132]
#pragma unroll
        for (int i = 0; i < 2; i++)
#pragma unroll
            for (int j = 0; j < 12; j++)
#pragma unroll
                for (int h = 0; h < 2; h++) {
                    int row = wr * 32 + 16 * i + rr + 8 * h;
                    int col = wh * 96 + 8 * j + cc;
                    sT[col * 132 + row]       = acc[i][j][2 * h + 0];
                    sT[(col + 1) * 132 + row] = acc[i][j][2 * h + 1];
                }
        __syncthreads();
        for (int task = tid; task < 3072; task += 256) {
            int cl = task >> 4, ch8 = task & 15;
            int k = cl >> 6, o = cl & 63;
            const float* src = &sT[cl * 132 + ch8 * 8];
            size_t gi = ((size_t)bb * TO_ + tt * 64 + o) * N_ + n0 + ch8 * 8;
            if (k == 0) {
                *(float4*)&g_Dt[gi]     = make_float4(src[0], src[1], src[2], src[3]);
                *(float4*)&g_Dt[gi + 4] = make_float4(src[4], src[5], src[6], src[7]);
            } else if (k == 1) {
                const float* s2 = &sT[(cl + 64) * 132 + ch8 * 8];
                *(float4*)&g_R1p[gi]     = make_float4(src[0] - 2.f * s2[0], src[1] - 2.f * s2[1],
                                                       src[2] - 2.f * s2[2], src[3] - 2.f * s2[3]);
                *(float4*)&g_R1p[gi + 4] = make_float4(src[4] - 2.f * s2[4], src[5] - 2.f * s2[5],
                                                       src[6] - 2.f * s2[6], src[7] - 2.f * s2[7]);
            } else {
                unsigned p0 = pack2h(src[0], src[1]), p1 = pack2h(src[2], src[3]);
                unsigned p2 = pack2h(src[4], src[5]), p3 = pack2h(src[6], src[7]);
                *(uint4*)&g_R2f[gi] = make_uint4(p0, p1, p2, p3);
            }
        }
    }
}

// ---------------- HMMA GEMM: C[128x128] = A[b] @ Bsrc[b], SINGLE-product fp16 ----------------
// 256 threads, 2x4 warps, 64x32 warp tiles, 3-stage BK=64, 96KB smem -> 2 CTAs/SM
#define SB_  16384
#define STAGE_BYTES 32768
#define GEMM_SMEM   (3 * STAGE_BYTES)

__device__ __forceinline__ void fill_stage(uint32_t st, int kt, int bm0, int bn0,
                                           const __half* __restrict__ Af,
                                           const __half* __restrict__ Bs, int tid) {
    int ch = tid & 7, r0 = tid >> 3;   // r0: 0..31
#pragma unroll
    for (int i = 0; i < 4; i++) {
        int row = r0 + 32 * i;
        uint32_t sw = (uint32_t)(row * 128 + ((ch ^ (row & 7)) << 4));
        size_t ao = (size_t)(bm0 + row) * N_ + kt + ch * 8;
        size_t bo = (size_t)(bn0 + row) * N_ + kt + ch * 8;
        CP16(st + sw,       Af + ao);
        CP16(st + SB_ + sw, Bs + bo);
    }
}

template <int MODE>
__global__ __launch_bounds__(256, 2) void gemm_hmma(float* __restrict__ out) {
    extern __shared__ __align__(1024) char smem[];
    uint32_t sb = smem_u32(smem);
    int tid = threadIdx.x, lane = tid & 31, wid = tid >> 5;
    int wm = wid & 1, wn = wid >> 1;     // 2x4 warps; warp tile 64 rows x 32 cols
    int b = blockIdx.z, bm0 = blockIdx.y * 128, bn0 = blockIdx.x * 128;

    const __half* Agf = g_Af + ((size_t)b << 20);
    const __half* Bgs = (MODE == 1) ? (g_R2f + (size_t)b * TO_ * N_) : (g_Zf16 + (size_t)b * TO_ * N_);

    float acc[4][4][4];
#pragma unroll
    for (int i = 0; i < 4; i++)
#pragma unroll
        for (int j = 0; j < 4; j++)
#pragma unroll
            for (int q = 0; q < 4; q++) acc[i][j][q] = 0.f;

    int a_r = (lane & 7) + ((lane >> 3) & 1) * 8;
    int a_c = lane >> 4;
    int b_r = (lane & 7) + (lane >> 4) * 8;
    int b_c = (lane >> 3) & 1;

    int rowA[4], rowB[2];
#pragma unroll
    for (int i = 0; i < 4; i++) rowA[i] = wm * 64 + 16 * i + a_r;
#pragma unroll
    for (int j2 = 0; j2 < 2; j2++) rowB[j2] = wn * 32 + 16 * j2 + b_r;

#pragma unroll
    for (int c = 0; c < 3; c++) {
        fill_stage(sb + c * STAGE_BYTES, c * 64, bm0, bn0, Agf, Bgs, tid);
        CP_COMMIT();
    }

    for (int c = 0; c < 16; c++) {
        uint32_t stage = sb + (uint32_t)(c % 3) * STAGE_BYTES;
        if (c <= 13)      CP_WAIT(2);
        else if (c == 14) CP_WAIT(1);
        else              CP_WAIT(0);
        __syncthreads();

#pragma unroll
        for (int kk = 0; kk < 4; kk++) {
            unsigned af[4][4], bf[2][4];
#pragma unroll
            for (int i = 0; i < 4; i++) {
                uint32_t ad = stage + (uint32_t)(rowA[i] * 128 +
                    (((kk * 2 + a_c) ^ (rowA[i] & 7)) << 4));
                ldsm4(af[i], ad);
            }
#pragma unroll
            for (int j2 = 0; j2 < 2; j2++) {
                uint32_t bd = stage + SB_ + (uint32_t)(rowB[j2] * 128 +
                    (((kk * 2 + b_c) ^ (rowB[j2] & 7)) << 4));
                ldsm4(bf[j2], bd);
            }
#pragma unroll
            for (int i = 0; i < 4; i++)
#pragma unroll
                for (int j = 0; j < 4; j++)
                    mma16816(acc[i][j], af[i], &bf[j >> 1][(j & 1) * 2]);
        }

        // refill the just-consumed buffer (3-stage ring) for k-chunk c+3
        if (c + 3 < 16) {
            __syncthreads();
            fill_stage(stage, (c + 3) * 64, bm0, bn0, Agf, Bgs, tid);
            CP_COMMIT();
        }
    }

    // ---------------- epilogue ----------------
    float lam = g_lam[b];
    int m0 = bm0 + wm * 64, to0 = bn0 + wn * 32;
    int rr = lane >> 2, cc = (lane & 3) * 2;

    if (MODE == 1) {
        float s4 = 4.0f / lam;
#pragma unroll
        for (int i = 0; i < 4; i++)
#pragma unroll
            for (int j = 0; j < 4; j++)
#pragma unroll
                for (int h = 0; h < 2; h++) {
                    int n = m0 + 16 * i + rr + 8 * h;
#pragma unroll
                    for (int q = 0; q < 2; q++) {
                        int to = to0 + 8 * j + cc + q;
                        size_t bi = ((size_t)b * TO_ + to) * N_ + n;
                        float z = g_R1p[bi] + s4 * acc[i][j][2 * h + q];
                        g_Zf[bi] = z;
                        g_Zf16[bi] = __float2half_rn(z);
                    }
                }
    } else {
        float s2 = 2.0f / lam;
        int t = to0 >> 6;
        int o0 = to0 & 63;
#pragma unroll
        for (int i = 0; i < 4; i++)
#pragma unroll
            for (int j = 0; j < 4; j++)
#pragma unroll
                for (int h = 0; h < 2; h++) {
                    int n = m0 + 16 * i + rr + 8 * h;
                    float2 v;
#pragma unroll
                    for (int q = 0; q < 2; q++) {
                        int to = to0 + 8 * j + cc + q;
                        size_t bi = ((size_t)b * TO_ + to) * N_ + n;
                        float val = g_Dt[bi] + s2 * acc[i][j][2 * h + q] - g_Zf[bi];
                        ((float*)&v)[q] = fmaxf(val, 0.f);
                    }
                    size_t oi = ((size_t)(b * T_ + t) * N_ + n) * 64 + o0 + 8 * j + cc;
                    *(float2*)&out[oi] = v;
                }
    }
}

// ---------------- launch ----------------
extern "C" void kernel_launch(void* const* d_in, const int* in_sizes, int n_in,
                              void* d_out, int out_size) {
    const float* x = nullptr;
    const float* A = nullptr;
    const float* Th = nullptr;
    for (int i = 0; i < n_in; i++) {
        if (in_sizes[i] == B_ * N_ * N_)           A  = (const float*)d_in[i];
        else if (in_sizes[i] == B_ * T_ * N_ * F_) x  = (const float*)d_in[i];
        else if (in_sizes[i] == 3 * F_ * 64)       Th = (const float*)d_in[i];
    }
    float* out = (float*)d_out;

    cudaFuncSetAttribute(gemm_hmma<1>, cudaFuncAttributeMaxDynamicSharedMemorySize, GEMM_SMEM);
    cudaFuncSetAttribute(gemm_hmma<2>, cudaFuncAttributeMaxDynamicSharedMemorySize, GEMM_SMEM);
    cudaFuncSetAttribute(feat_mma, cudaFuncAttributeMaxDynamicSharedMemorySize, FEAT_SMEM);

    lam_init_kernel<<<1, 32>>>();
    rowsum_conv_kernel<<<B_ * N_, 256>>>(A);
    feat_mma<<<(B_ * T_ * N_) / 512, 256, FEAT_SMEM>>>(x, Th);
    dim3 gg(TO_ / 128, N_ / 128, B_);
    gemm_hmma<1><<<gg, 256, GEMM_SMEM>>>(out);
    gemm_hmma<2><<<gg, 256, GEMM_SMEM>>>(out);
}